// round 2
// baseline (speedup 1.0000x reference)
#include <cuda_runtime.h>
#include <cstdint>

#define NN 50000
#define NE 400000
#define DIM 128

// Scratch (allocation-free rule: __device__ globals)
__device__ float g_h[NN * DIM];
__device__ float g_agg[NN * DIM];
__device__ float g_deg[NN];

// ---------------------------------------------------------------------------
// Tiled fp32 GEMM: C[m,n] = act( sum_k A[m,k] * W[n,k] + bias[n] )
// BM=128, BN=128, BK=32, 256 threads, 8x8 microtile per thread.
// MODE 0: A = param A (x), relu, C = g_h
// MODE 1: A = g_agg * inv(max(deg,1)) + g_h, no relu, C = param C (d_out)
// ---------------------------------------------------------------------------
template <int MODE>
__global__ __launch_bounds__(256, 2)
void gemm_kernel(const float* __restrict__ A,
                 const float* __restrict__ W,
                 const float* __restrict__ bias,
                 float* __restrict__ C)
{
    __shared__ float Xs[32][132];
    __shared__ float Ws[32][132];

    const int tid = threadIdx.x;
    const int m0  = blockIdx.x * 128;

    const int lc = tid & 7;    // k-group (4 floats)
    const int lr = tid >> 3;   // row within 32-row slab

    const int tx = tid & 15;   // col thread
    const int ty = tid >> 4;   // row thread

    float acc[8][8];
#pragma unroll
    for (int i = 0; i < 8; i++)
#pragma unroll
        for (int j = 0; j < 8; j++) acc[i][j] = 0.0f;

    for (int k0 = 0; k0 < DIM; k0 += 32) {
        // ---- load A tile (transposed into Xs[k][m]) ----
#pragma unroll
        for (int s = 0; s < 4; s++) {
            int m  = lr + s * 32;
            int gm = m0 + m;
            float4 v = make_float4(0.f, 0.f, 0.f, 0.f);
            if (gm < NN) {
                int idx = gm * DIM + k0 + lc * 4;
                if (MODE == 0) {
                    v = *(const float4*)&A[idx];
                } else {
                    float d   = g_deg[gm];
                    float inv = 1.0f / fmaxf(d, 1.0f);
                    float4 ag = *(const float4*)&g_agg[idx];
                    float4 hh = *(const float4*)&g_h[idx];
                    v.x = fmaf(ag.x, inv, hh.x);
                    v.y = fmaf(ag.y, inv, hh.y);
                    v.z = fmaf(ag.z, inv, hh.z);
                    v.w = fmaf(ag.w, inv, hh.w);
                }
            }
            Xs[lc * 4 + 0][m] = v.x;
            Xs[lc * 4 + 1][m] = v.y;
            Xs[lc * 4 + 2][m] = v.z;
            Xs[lc * 4 + 3][m] = v.w;
        }
        // ---- load W tile (transposed into Ws[k][n]) ----
#pragma unroll
        for (int s = 0; s < 4; s++) {
            int n = lr + s * 32;
            float4 v = *(const float4*)&W[n * DIM + k0 + lc * 4];
            Ws[lc * 4 + 0][n] = v.x;
            Ws[lc * 4 + 1][n] = v.y;
            Ws[lc * 4 + 2][n] = v.z;
            Ws[lc * 4 + 3][n] = v.w;
        }
        __syncthreads();

        // ---- compute ----
#pragma unroll
        for (int kk = 0; kk < 32; kk++) {
            float a[8], b[8];
            float4 t;
            t = *(const float4*)&Xs[kk][ty * 8];     a[0]=t.x; a[1]=t.y; a[2]=t.z; a[3]=t.w;
            t = *(const float4*)&Xs[kk][ty * 8 + 4]; a[4]=t.x; a[5]=t.y; a[6]=t.z; a[7]=t.w;
            t = *(const float4*)&Ws[kk][tx * 8];     b[0]=t.x; b[1]=t.y; b[2]=t.z; b[3]=t.w;
            t = *(const float4*)&Ws[kk][tx * 8 + 4]; b[4]=t.x; b[5]=t.y; b[6]=t.z; b[7]=t.w;
#pragma unroll
            for (int i = 0; i < 8; i++)
#pragma unroll
                for (int j = 0; j < 8; j++)
                    acc[i][j] = fmaf(a[i], b[j], acc[i][j]);
        }
        __syncthreads();
    }

    // ---- epilogue ----
    float* Cout = (MODE == 0) ? g_h : C;
#pragma unroll
    for (int i = 0; i < 8; i++) {
        int gm = m0 + ty * 8 + i;
        if (gm < NN) {
#pragma unroll
            for (int j = 0; j < 8; j += 4) {
                int n = tx * 8 + j;
                float4 o;
                o.x = acc[i][j + 0] + bias[n + 0];
                o.y = acc[i][j + 1] + bias[n + 1];
                o.z = acc[i][j + 2] + bias[n + 2];
                o.w = acc[i][j + 3] + bias[n + 3];
                if (MODE == 0) {
                    o.x = fmaxf(o.x, 0.f);
                    o.y = fmaxf(o.y, 0.f);
                    o.z = fmaxf(o.z, 0.f);
                    o.w = fmaxf(o.w, 0.f);
                }
                *(float4*)&Cout[gm * DIM + n] = o;
            }
        }
    }
}

// ---------------------------------------------------------------------------
// Scatter: one warp per edge. Lane l reads float4 of h[src], red.add.v4 into
// agg[dst]. Lane 0 bumps deg[dst].  edge_index is int32 (JAX x64 disabled).
// ---------------------------------------------------------------------------
__global__ __launch_bounds__(256)
void scatter_kernel(const int* __restrict__ ei)
{
    int w    = (blockIdx.x * blockDim.x + threadIdx.x) >> 5;
    int lane = threadIdx.x & 31;
    if (w >= NE) return;

    int s = ei[w];
    int d = ei[NE + w];
    // clamp (branch-free safety; indices should already be in [0, NN))
    s = min(max(s, 0), NN - 1);
    d = min(max(d, 0), NN - 1);

    const float4* hrow = (const float4*)&g_h[(size_t)s * DIM];
    float4 v = hrow[lane];

    float* dstp = &g_agg[(size_t)d * DIM + lane * 4];
    asm volatile("red.global.add.v4.f32 [%0], {%1, %2, %3, %4};"
                 :: "l"(dstp), "f"(v.x), "f"(v.y), "f"(v.z), "f"(v.w)
                 : "memory");

    if (lane == 0) atomicAdd(&g_deg[d], 1.0f);
}

// ---------------------------------------------------------------------------
extern "C" void kernel_launch(void* const* d_in, const int* in_sizes, int n_in,
                              void* d_out, int out_size)
{
    const float* x  = (const float*)d_in[0];
    const int*   ei = (const int*)d_in[1];
    const float* W1 = (const float*)d_in[2];
    const float* b1 = (const float*)d_in[3];
    const float* W2 = (const float*)d_in[4];
    const float* b2 = (const float*)d_in[5];
    float*       out = (float*)d_out;

    void* aggp = nullptr;
    void* degp = nullptr;
    cudaGetSymbolAddress(&aggp, g_agg);
    cudaGetSymbolAddress(&degp, g_deg);
    cudaMemsetAsync(aggp, 0, (size_t)NN * DIM * sizeof(float));
    cudaMemsetAsync(degp, 0, (size_t)NN * sizeof(float));

    int mtiles = (NN + 127) / 128;

    // h = relu(x @ W1^T + b1) -> g_h
    gemm_kernel<0><<<mtiles, 256>>>(x, W1, b1, nullptr);

    // agg += h[src] per edge; deg += 1
    long long total_threads = (long long)NE * 32;
    int blocks = (int)((total_threads + 255) / 256);
    scatter_kernel<<<blocks, 256>>>(ei);

    // out = (agg/deg + h) @ W2^T + b2
    gemm_kernel<1><<<mtiles, 256>>>(nullptr, W2, b2, out);
}

// round 4
// speedup vs baseline: 1.1514x; 1.1514x over previous
#include <cuda_runtime.h>
#include <cstdint>

#define NN 50000
#define NE 400000
#define DIM 128
#define SSTRIDE 36   // smem row stride (floats): 4*m+k bank pattern -> conflict-free frag loads

// Scratch (allocation-free rule: __device__ globals)
__device__ float g_h[NN * DIM];
__device__ float g_agg[NN * DIM];
__device__ float g_deg[NN];

// ---------------------------------------------------------------------------
// tf32 helpers
// ---------------------------------------------------------------------------
__device__ __forceinline__ void split_tf32(float a, uint32_t& hi, uint32_t& lo)
{
    uint32_t h;
    asm("cvt.rna.tf32.f32 %0, %1;" : "=r"(h) : "f"(a));
    float r = a - __uint_as_float(h);          // exact in f32
    asm("cvt.rna.tf32.f32 %0, %1;" : "=r"(lo) : "f"(r));
    hi = h;
}

__device__ __forceinline__ void mma8(float* c,
                                     uint32_t a0, uint32_t a1, uint32_t a2, uint32_t a3,
                                     uint32_t b0, uint32_t b1)
{
    asm volatile(
        "mma.sync.aligned.m16n8k8.row.col.f32.tf32.tf32.f32 "
        "{%0,%1,%2,%3}, {%4,%5,%6,%7}, {%8,%9}, {%0,%1,%2,%3};"
        : "+f"(c[0]), "+f"(c[1]), "+f"(c[2]), "+f"(c[3])
        : "r"(a0), "r"(a1), "r"(a2), "r"(a3), "r"(b0), "r"(b1));
}

// ---------------------------------------------------------------------------
// Tensor-core GEMM: C[m,n] = act( sum_k A[m,k] * W[n,k] + bias[n] )
// BM=128, BN=128 (full), K=128 in 4 slabs of 32. 256 threads = 8 warps (4x2).
// 3-pass tf32 split => ~fp32 accuracy.
// MODE 0: A = x, relu, C = g_h
// MODE 1: A = g_agg/max(deg,1) + g_h (fused on load), C = d_out
// ---------------------------------------------------------------------------
template <int MODE>
__global__ __launch_bounds__(256, 2)
void gemm_tc(const float* __restrict__ A,
             const float* __restrict__ W,
             const float* __restrict__ bias,
             float* __restrict__ C)
{
    __shared__ float As[128 * SSTRIDE];
    __shared__ float Ws[128 * SSTRIDE];

    const int tid    = threadIdx.x;
    const int lane   = tid & 31;
    const int wid    = tid >> 5;
    const int warp_m = wid >> 1;   // 0..3 -> 32-row band
    const int warp_n = wid & 1;    // 0..1 -> 64-col band
    const int m0     = blockIdx.x * 128;

    float acc[2][8][4];
#pragma unroll
    for (int mt = 0; mt < 2; mt++)
#pragma unroll
        for (int nt = 0; nt < 8; nt++)
#pragma unroll
            for (int i = 0; i < 4; i++) acc[mt][nt][i] = 0.0f;

    const int srow = tid >> 3;          // 0..31
    const int scol = (tid & 7) * 4;     // 0,4,...,28

    for (int k0 = 0; k0 < DIM; k0 += 32) {
        // ---- stage A and W slabs (raw f32) ----
#pragma unroll
        for (int s = 0; s < 4; s++) {
            int row = srow + s * 32;    // 0..127
            int gm  = m0 + row;
            float4 v = make_float4(0.f, 0.f, 0.f, 0.f);
            if (gm < NN) {
                int gi = gm * DIM + k0 + scol;
                if (MODE == 0) {
                    v = *(const float4*)&A[gi];
                } else {
                    float d   = g_deg[gm];
                    float inv = 1.0f / fmaxf(d, 1.0f);
                    float4 ag = *(const float4*)&g_agg[gi];
                    float4 hh = *(const float4*)&g_h[gi];
                    v.x = fmaf(ag.x, inv, hh.x);
                    v.y = fmaf(ag.y, inv, hh.y);
                    v.z = fmaf(ag.z, inv, hh.z);
                    v.w = fmaf(ag.w, inv, hh.w);
                }
            }
            *(float4*)&As[row * SSTRIDE + scol] = v;

            float4 wv = *(const float4*)&W[row * DIM + k0 + scol];
            *(float4*)&Ws[row * SSTRIDE + scol] = wv;
        }
        __syncthreads();

        // ---- 4 k-steps of 8 ----
#pragma unroll
        for (int ks = 0; ks < 4; ks++) {
            const int kk = ks * 8 + (lane & 3);

            uint32_t Ahi[2][4], Alo[2][4];
#pragma unroll
            for (int mt = 0; mt < 2; mt++) {
                int r0 = warp_m * 32 + mt * 16 + (lane >> 2);
                float ra0 = As[r0 * SSTRIDE + kk];
                float ra1 = As[(r0 + 8) * SSTRIDE + kk];
                float ra2 = As[r0 * SSTRIDE + kk + 4];
                float ra3 = As[(r0 + 8) * SSTRIDE + kk + 4];
                split_tf32(ra0, Ahi[mt][0], Alo[mt][0]);
                split_tf32(ra1, Ahi[mt][1], Alo[mt][1]);
                split_tf32(ra2, Ahi[mt][2], Alo[mt][2]);
                split_tf32(ra3, Ahi[mt][3], Alo[mt][3]);
            }

#pragma unroll
            for (int nt = 0; nt < 8; nt++) {
                int n0 = warp_n * 64 + nt * 8 + (lane >> 2);
                float rb0 = Ws[n0 * SSTRIDE + kk];
                float rb1 = Ws[n0 * SSTRIDE + kk + 4];
                uint32_t Bhi0, Blo0, Bhi1, Blo1;
                split_tf32(rb0, Bhi0, Blo0);
                split_tf32(rb1, Bhi1, Blo1);
#pragma unroll
                for (int mt = 0; mt < 2; mt++) {
                    mma8(acc[mt][nt], Ahi[mt][0], Ahi[mt][1], Ahi[mt][2], Ahi[mt][3], Bhi0, Bhi1);
                    mma8(acc[mt][nt], Ahi[mt][0], Ahi[mt][1], Ahi[mt][2], Ahi[mt][3], Blo0, Blo1);
                    mma8(acc[mt][nt], Alo[mt][0], Alo[mt][1], Alo[mt][2], Alo[mt][3], Bhi0, Bhi1);
                }
            }
        }
        __syncthreads();
    }

    // ---- epilogue ----
    float* Cout = (MODE == 0) ? g_h : C;
#pragma unroll
    for (int mt = 0; mt < 2; mt++) {
#pragma unroll
        for (int nt = 0; nt < 8; nt++) {
            int row0 = m0 + warp_m * 32 + mt * 16 + (lane >> 2);
            int col  = warp_n * 64 + nt * 8 + 2 * (lane & 3);
            float2 bv = *(const float2*)&bias[col];
            float o0 = acc[mt][nt][0] + bv.x;
            float o1 = acc[mt][nt][1] + bv.y;
            float o2 = acc[mt][nt][2] + bv.x;
            float o3 = acc[mt][nt][3] + bv.y;
            if (MODE == 0) {
                o0 = fmaxf(o0, 0.f); o1 = fmaxf(o1, 0.f);
                o2 = fmaxf(o2, 0.f); o3 = fmaxf(o3, 0.f);
            }
            if (row0 < NN) {
                float2 w0 = {o0, o1};
                *(float2*)&Cout[row0 * DIM + col] = w0;
            }
            if (row0 + 8 < NN) {
                float2 w1 = {o2, o3};
                *(float2*)&Cout[(row0 + 8) * DIM + col] = w1;
            }
        }
    }
}

// ---------------------------------------------------------------------------
// Scatter: one warp per edge. Lane l reads float4 of h[src], red.add.v4 into
// agg[dst]. Lane 0 bumps deg[dst]. edge_index is int32.
// ---------------------------------------------------------------------------
__global__ __launch_bounds__(256)
void scatter_kernel(const int* __restrict__ ei)
{
    int w    = (blockIdx.x * blockDim.x + threadIdx.x) >> 5;
    int lane = threadIdx.x & 31;
    if (w >= NE) return;

    int s = ei[w];
    int d = ei[NE + w];
    s = min(max(s, 0), NN - 1);
    d = min(max(d, 0), NN - 1);

    const float4* hrow = (const float4*)&g_h[(size_t)s * DIM];
    float4 v = hrow[lane];

    float* dstp = &g_agg[(size_t)d * DIM + lane * 4];
    asm volatile("red.global.add.v4.f32 [%0], {%1, %2, %3, %4};"
                 :: "l"(dstp), "f"(v.x), "f"(v.y), "f"(v.z), "f"(v.w)
                 : "memory");

    if (lane == 0) atomicAdd(&g_deg[d], 1.0f);
}

// ---------------------------------------------------------------------------
extern "C" void kernel_launch(void* const* d_in, const int* in_sizes, int n_in,
                              void* d_out, int out_size)
{
    const float* x  = (const float*)d_in[0];
    const int*   ei = (const int*)d_in[1];
    const float* W1 = (const float*)d_in[2];
    const float* b1 = (const float*)d_in[3];
    const float* W2 = (const float*)d_in[4];
    const float* b2 = (const float*)d_in[5];
    float*       out = (float*)d_out;

    void* aggp = nullptr;
    void* degp = nullptr;
    cudaGetSymbolAddress(&aggp, g_agg);
    cudaGetSymbolAddress(&degp, g_deg);
    cudaMemsetAsync(aggp, 0, (size_t)NN * DIM * sizeof(float));
    cudaMemsetAsync(degp, 0, (size_t)NN * sizeof(float));

    int mtiles = (NN + 127) / 128;

    // h = relu(x @ W1^T + b1) -> g_h
    gemm_tc<0><<<mtiles, 256>>>(x, W1, b1, nullptr);

    // agg += h[src] per edge; deg += 1
    long long total_threads = (long long)NE * 32;
    int blocks = (int)((total_threads + 255) / 256);
    scatter_kernel<<<blocks, 256>>>(ei);

    // out = (agg/deg + h) @ W2^T + b2
    gemm_tc<1><<<mtiles, 256>>>(nullptr, W2, b2, out);
}